// round 4
// baseline (speedup 1.0000x reference)
#include <cuda_runtime.h>
#include <cstdint>

// out[dst[e]] += (w_mp * ew[e]) * x[src[e]]   for e in [0, E)
// x: [N, 32] f32
// edge_index: [2, E] int32  (JAX default x64-disabled downcasts the declared int64)
// ew: [E] f32, w_mp: [1] f32
// out: [N, 32] f32

__global__ void zero_kernel(float4* __restrict__ out, int n4) {
    int i = blockIdx.x * blockDim.x + threadIdx.x;
    if (i < n4) out[i] = make_float4(0.f, 0.f, 0.f, 0.f);
}

__global__ __launch_bounds__(256)
void scatter_kernel(const float* __restrict__ x,
                    const int* __restrict__ edge_index,
                    const float* __restrict__ ew,
                    const float* __restrict__ w_mp,
                    float* __restrict__ out,
                    int E) {
    // 8 lanes per edge; lane c owns float4 chunk c of the 32-float row.
    int tid = blockIdx.x * blockDim.x + threadIdx.x;
    int e = tid >> 3;
    int c = tid & 7;
    if (e >= E) return;

    int s = __ldg(&edge_index[e]);
    int d = __ldg(&edge_index[E + e]);
    float w = __ldg(&ew[e]) * __ldg(w_mp);

    // Coalesced 128B row read (row is 128B-aligned: 32 floats)
    float4 v = __ldg(reinterpret_cast<const float4*>(x + (long long)s * 32) + c);
    v.x *= w; v.y *= w; v.z *= w; v.w *= w;

    float* dst = out + (long long)d * 32 + c * 4;
    asm volatile("red.global.add.v4.f32 [%0], {%1, %2, %3, %4};"
                 :: "l"(dst), "f"(v.x), "f"(v.y), "f"(v.z), "f"(v.w)
                 : "memory");
}

extern "C" void kernel_launch(void* const* d_in, const int* in_sizes, int n_in,
                              void* d_out, int out_size) {
    const float* x    = (const float*)d_in[0];
    const int*   ei   = (const int*)d_in[1];
    const float* ew   = (const float*)d_in[2];
    const float* w_mp = (const float*)d_in[3];
    float* out = (float*)d_out;

    int E = in_sizes[2];          // edge_weight has E elements
    int n4 = out_size / 4;        // out_size = N*32 floats

    zero_kernel<<<(n4 + 255) / 256, 256>>>((float4*)out, n4);

    long long threads = (long long)E * 8;
    int blocks = (int)((threads + 255) / 256);
    scatter_kernel<<<blocks, 256>>>(x, ei, ew, w_mp, out, E);
}